// round 5
// baseline (speedup 1.0000x reference)
#include <cuda_runtime.h>
#include <math.h>

// ---------------- problem constants ----------------
constexpr int kB    = 64;
constexpr int kSVIT = 257;
constexpr int kSQ   = 32;
constexpr int kL    = 512;
constexpr int kIMG  = 1408;
constexpr int kHID  = 768;
constexpr int kC    = 30000;
constexpr int kHC   = 32;   // H_CLUB
constexpr int kHM   = 64;   // H_MINE

// ---------------- scratch (device globals; no allocation) ----------------
__device__ __align__(16) float  g_hist[kB * kC];
__device__ __align__(16) float  g_xv[kB * kIMG];
__device__ __align__(16) float  g_xq[kB * kHID];
__device__ __align__(16) float  g_hmu[kB * kHC];
__device__ __align__(16) float  g_hlv[kB * kHC];
__device__ float  g_T0[kB];
__device__ float  g_T1[kB];
__device__ double g_acc;

// ---------------- K0: zero hist + accumulator ----------------
__global__ void k_zero() {
    int idx = blockIdx.x * blockDim.x + threadIdx.x;
    float4* p = reinterpret_cast<float4*>(g_hist);
    if (idx < (kB * kC) / 4) p[idx] = make_float4(0.f, 0.f, 0.f, 0.f);
    if (idx == 0) g_acc = 0.0;
}

// ---------------- K1: scatter labels into histogram ----------------
__global__ void k_scatter(const int* __restrict__ label) {
    int i = blockIdx.x * blockDim.x + threadIdx.x;
    if (i < kB * kL) {
        int l = label[i];
        if (l == -100) l = 0;
        int b = i / kL;
        atomicAdd(&g_hist[b * kC + l], 1.0f);
    }
}

// ---------------- K2: vit mean over axis 1 (92MB read) ----------------
__global__ void k_vit_mean(const float* __restrict__ vit) {
    int d = blockIdx.x * blockDim.x + threadIdx.x;
    int b = blockIdx.y;
    const float* p = vit + (size_t)b * kSVIT * kIMG + d;
    float a0=0,a1=0,a2=0,a3=0,a4=0,a5=0,a6=0,a7=0;
    int s = 0;
    for (; s + 8 <= kSVIT; s += 8) {
        a0 += p[(size_t)(s+0) * kIMG];
        a1 += p[(size_t)(s+1) * kIMG];
        a2 += p[(size_t)(s+2) * kIMG];
        a3 += p[(size_t)(s+3) * kIMG];
        a4 += p[(size_t)(s+4) * kIMG];
        a5 += p[(size_t)(s+5) * kIMG];
        a6 += p[(size_t)(s+6) * kIMG];
        a7 += p[(size_t)(s+7) * kIMG];
    }
    for (; s < kSVIT; s++) a0 += p[(size_t)s * kIMG];
    float sum = ((a0+a1)+(a2+a3)) + ((a4+a5)+(a6+a7));
    g_xv[b * kIMG + d] = sum / (float)kSVIT;
}

// ---------------- K3: qformer mean over axis 1 ----------------
__global__ void k_q_mean(const float* __restrict__ qf) {
    int d = blockIdx.x * blockDim.x + threadIdx.x;
    int b = blockIdx.y;
    const float* p = qf + (size_t)b * kSQ * kHID + d;
    float a0=0,a1=0,a2=0,a3=0;
    #pragma unroll
    for (int s = 0; s < kSQ; s += 4) {
        a0 += p[(s+0) * kHID];
        a1 += p[(s+1) * kHID];
        a2 += p[(s+2) * kHID];
        a3 += p[(s+3) * kHID];
    }
    g_xq[b * kHID + d] = ((a0+a1)+(a2+a3)) / (float)kSQ;
}

// ---------------- K4: small MLP heads (exact fp32 FMA, no tf32) ---------
__global__ void k_heads(const float* __restrict__ Wmu1, const float* __restrict__ bmu1,
                        const float* __restrict__ Wlv1, const float* __restrict__ blv1,
                        const float* __restrict__ Wt1,  const float* __restrict__ bt1,
                        const float* __restrict__ Wt2,  const float* __restrict__ bt2,
                        const int*   __restrict__ rand_idx) {
    int b = blockIdx.x, t = threadIdx.x;
    __shared__ float s_h0[kHM], s_h1[kHM];

    if (t < 64) {
        int j = t & 31;
        const float* W  = (t < 32) ? Wmu1 : Wlv1;
        const float* bb = (t < 32) ? bmu1 : blv1;
        const float* xq = g_xq + b * kHID;
        float a0 = 0.f, a1 = 0.f, a2 = 0.f, a3 = 0.f;
        for (int k = 0; k < kHID; k += 4) {
            a0 = fmaf(xq[k+0], W[(k+0) * kHC + j], a0);
            a1 = fmaf(xq[k+1], W[(k+1) * kHC + j], a1);
            a2 = fmaf(xq[k+2], W[(k+2) * kHC + j], a2);
            a3 = fmaf(xq[k+3], W[(k+3) * kHC + j], a3);
        }
        float h = fmaxf((((a0+a1)+(a2+a3)) + bb[j]), 0.f);
        if (t < 32) g_hmu[b * kHC + j] = h;
        else        g_hlv[b * kHC + j] = h;
    } else {
        int u = (t - 64) & 63;
        int qrow = (t < 128) ? b : rand_idx[b];
        const float* xv = g_xv + (size_t)b    * kIMG;
        const float* xq = g_xq + (size_t)qrow * kHID;
        float a0 = 0.f, a1 = 0.f, a2 = 0.f, a3 = 0.f;
        for (int k = 0; k < kIMG; k += 4) {
            a0 = fmaf(xv[k+0], Wt1[(k+0) * kHM + u], a0);
            a1 = fmaf(xv[k+1], Wt1[(k+1) * kHM + u], a1);
            a2 = fmaf(xv[k+2], Wt1[(k+2) * kHM + u], a2);
            a3 = fmaf(xv[k+3], Wt1[(k+3) * kHM + u], a3);
        }
        for (int k = 0; k < kHID; k += 4) {
            a0 = fmaf(xq[k+0], Wt1[(kIMG+k+0) * kHM + u], a0);
            a1 = fmaf(xq[k+1], Wt1[(kIMG+k+1) * kHM + u], a1);
            a2 = fmaf(xq[k+2], Wt1[(kIMG+k+2) * kHM + u], a2);
            a3 = fmaf(xq[k+3], Wt1[(kIMG+k+3) * kHM + u], a3);
        }
        float h = fmaxf((((a0+a1)+(a2+a3)) + bt1[u]), 0.f);
        if (t < 128) s_h0[u] = h;
        else         s_h1[u] = h;
    }
    __syncthreads();
    // T0/T1 final dot: sequential fp32 FMA (k-order), bias after
    if (t == 0) {
        float a = 0.f, c2 = 0.f;
        for (int u = 0; u < kHM; u++) {
            float w = Wt2[u];
            a  = fmaf(s_h0[u], w, a);
            c2 = fmaf(s_h1[u], w, c2);
        }
        g_T0[b] = a  + bt2[0];
        g_T1[b] = c2 + bt2[0];
    }
}

// ---------------- K5: I_zy — sparse-aware scan over (b,c), fp32 terms ----
__global__ void k_izy(const float* __restrict__ Wmu2, const float* __restrict__ bmu2,
                      const float* __restrict__ Wlv2, const float* __restrict__ blv2,
                      const int*   __restrict__ perm_idx) {
    __shared__ float s_hmu[kB * kHC];
    __shared__ float s_hlv[kB * kHC];
    __shared__ int   s_perm[kB];
    int tx = threadIdx.x;
    for (int i = tx; i < kB * kHC; i += blockDim.x) {
        s_hmu[i] = g_hmu[i];
        s_hlv[i] = g_hlv[i];
    }
    if (tx < kB) s_perm[tx] = perm_idx[tx];
    __syncthreads();

    int c = blockIdx.x * blockDim.x + tx;
    double acc = 0.0;
    if (c < kC) {
        float wm[kHC], wl[kHC];
        #pragma unroll
        for (int j = 0; j < kHC; j++) {
            wm[j] = Wmu2[j * kC + c];
            wl[j] = Wlv2[j * kC + c];
        }
        float bm = bmu2[c], bl = blv2[c];
        for (int b = 0; b < kB; b++) {
            float y  = g_hist[b * kC + c];
            float yp = g_hist[s_perm[b] * kC + c];
            if (y != 0.f || yp != 0.f) {
                y  *= (1.f / kL);
                yp *= (1.f / kL);
                float mu = 0.f, lv = 0.f;
                #pragma unroll
                for (int j = 0; j < kHC; j++) {
                    mu = fmaf(s_hmu[b * kHC + j], wm[j], mu);
                    lv = fmaf(s_hlv[b * kHC + j], wl[j], lv);
                }
                mu += bm;
                lv = tanhf(lv + bl);
                float iv = 1.f / (expf(lv) + 1e-6f);
                float dp = mu - y;
                float dn = mu - yp;
                acc += (double)((dn * dn - dp * dp) * iv);
            }
        }
    }

    __shared__ double red[128];
    red[tx] = acc;
    __syncthreads();
    for (int s = 64; s > 0; s >>= 1) {
        if (tx < s) red[tx] += red[tx + s];
        __syncthreads();
    }
    if (tx == 0) atomicAdd(&g_acc, red[0]);
}

// ---------------- K6: finalize — fp32 tail with correctly-rounded exp/log
// Replicates CPU-jax fp32 logsumexp: amax; e = fp32(exp(T1-amax));
// esum = strict sequential fp32 sum; lse = fp32(log(esum)) + amax;
// out = fp32 combine in reference order.
__global__ void k_final(float* __restrict__ out) {
    if (threadIdx.x == 0) {
        // amax (exact)
        float amax = g_T1[0];
        for (int b = 1; b < kB; b++) amax = fmaxf(amax, g_T1[b]);

        // correctly-rounded fp32 exp via double, strict sequential fp32 sums
        float esum = 0.f;
        float t0sum = 0.f;
        for (int b = 0; b < kB; b++) {
            float x = g_T1[b] - amax;                 // fp32 subtract
            float e = (float)exp((double)x);          // CR fp32 exp
            esum  = esum + e;                          // sequential fp32
            t0sum = t0sum + g_T0[b];                   // sequential fp32
        }
        float t0m  = t0sum / 64.0f;                    // exact /2^6
        float lgs  = (float)log((double)esum);         // CR fp32 log
        float lse  = lgs + amax;                       // fp32 add
        float logB = (float)log(64.0);                 // CR fp32 log(64)
        float d    = lse - logB;                       // fp32 cancel (as ref)
        float ixz  = t0m - d;                          // fp32
        float izy  = (float)g_acc / 128.0f;            // mean/2, exact halvings
        out[0] = izy - 0.1f * ixz;                     // fp32 final combine
    }
}

// ---------------- launch ----------------
extern "C" void kernel_launch(void* const* d_in, const int* in_sizes, int n_in,
                              void* d_out, int out_size) {
    const float* vit   = (const float*)d_in[0];
    const float* qf    = (const float*)d_in[1];
    const int*   label = (const int*)  d_in[2];
    const int*   perm  = (const int*)  d_in[3];
    const int*   rnd   = (const int*)  d_in[4];
    const float* Wmu1  = (const float*)d_in[5];
    const float* bmu1  = (const float*)d_in[6];
    const float* Wmu2  = (const float*)d_in[7];
    const float* bmu2  = (const float*)d_in[8];
    const float* Wlv1  = (const float*)d_in[9];
    const float* blv1  = (const float*)d_in[10];
    const float* Wlv2  = (const float*)d_in[11];
    const float* blv2  = (const float*)d_in[12];
    const float* Wt1   = (const float*)d_in[13];
    const float* bt1   = (const float*)d_in[14];
    const float* Wt2   = (const float*)d_in[15];
    const float* bt2   = (const float*)d_in[16];
    float* out = (float*)d_out;

    k_zero<<<(kB * kC / 4 + 255) / 256, 256>>>();
    k_scatter<<<(kB * kL + 255) / 256, 256>>>(label);
    k_vit_mean<<<dim3(kIMG / 128, kB), 128>>>(vit);
    k_q_mean<<<dim3(kHID / 128, kB), 128>>>(qf);
    k_heads<<<kB, 192>>>(Wmu1, bmu1, Wlv1, blv1, Wt1, bt1, Wt2, bt2, rnd);
    k_izy<<<(kC + 127) / 128, 128>>>(Wmu2, bmu2, Wlv2, blv2, perm);
    k_final<<<1, 32>>>(out);
}

// round 6
// speedup vs baseline: 1.0475x; 1.0475x over previous
#include <cuda_runtime.h>
#include <math.h>

// ---------------- problem constants ----------------
constexpr int kB    = 64;
constexpr int kSVIT = 257;
constexpr int kSQ   = 32;
constexpr int kL    = 512;
constexpr int kIMG  = 1408;
constexpr int kHID  = 768;
constexpr int kC    = 30000;
constexpr int kHC   = 32;   // H_CLUB
constexpr int kHM   = 64;   // H_MINE

constexpr int kIMG4 = kIMG / 4;   // 352 float4 columns
constexpr int kHID4 = kHID / 4;   // 192 float4 columns

// ---------------- scratch (device globals; no allocation) ----------------
__device__ __align__(16) float  g_hist[kB * kC];
__device__ __align__(16) float  g_xv[kB * kIMG];
__device__ __align__(16) float  g_xq[kB * kHID];
__device__ __align__(16) float  g_hmu[kB * kHC];
__device__ __align__(16) float  g_hlv[kB * kHC];
__device__ float  g_T0[kB];
__device__ float  g_T1[kB];
__device__ double g_acc;

__device__ __forceinline__ void f4add(float4& a, const float4 v) {
    a.x += v.x; a.y += v.y; a.z += v.z; a.w += v.w;
}

// ---------------- K0: zero hist + accumulator ----------------
__global__ void k_zero() {
    int idx = blockIdx.x * blockDim.x + threadIdx.x;
    float4* p = reinterpret_cast<float4*>(g_hist);
    if (idx < (kB * kC) / 4) p[idx] = make_float4(0.f, 0.f, 0.f, 0.f);
    if (idx == 0) g_acc = 0.0;
}

// ---------------- K1: scatter labels into histogram ----------------
__global__ void k_scatter(const int* __restrict__ label) {
    int i = blockIdx.x * blockDim.x + threadIdx.x;
    if (i < kB * kL) {
        int l = label[i];
        if (l == -100) l = 0;
        int b = i / kL;
        atomicAdd(&g_hist[b * kC + l], 1.0f);
    }
}

// ---------------- K2: vit mean over axis 1 (92MB read), float4 wide ------
// Per-column arithmetic identical to scalar version: accumulator a[i%8]
// gets s = i, i+8, ... in order; tail s=256 folds into a0; same add tree.
__global__ void __launch_bounds__(64) k_vit_mean(const float* __restrict__ vit) {
    int tid = blockIdx.x * 64 + threadIdx.x;          // 0 .. 64*352-1
    int b = tid / kIMG4;
    int c = tid % kIMG4;                              // float4 column
    const float4* p = reinterpret_cast<const float4*>(vit) + (size_t)b * kSVIT * kIMG4 + c;
    float4 a0 = make_float4(0,0,0,0), a1 = a0, a2 = a0, a3 = a0;
    float4 a4 = a0, a5 = a0, a6 = a0, a7 = a0;
    int s = 0;
    #pragma unroll 4
    for (; s + 8 <= kSVIT; s += 8) {
        f4add(a0, p[(size_t)(s+0) * kIMG4]);
        f4add(a1, p[(size_t)(s+1) * kIMG4]);
        f4add(a2, p[(size_t)(s+2) * kIMG4]);
        f4add(a3, p[(size_t)(s+3) * kIMG4]);
        f4add(a4, p[(size_t)(s+4) * kIMG4]);
        f4add(a5, p[(size_t)(s+5) * kIMG4]);
        f4add(a6, p[(size_t)(s+6) * kIMG4]);
        f4add(a7, p[(size_t)(s+7) * kIMG4]);
    }
    for (; s < kSVIT; s++) f4add(a0, p[(size_t)s * kIMG4]);
    float4 r;
    r.x = (((a0.x+a1.x)+(a2.x+a3.x)) + ((a4.x+a5.x)+(a6.x+a7.x))) / (float)kSVIT;
    r.y = (((a0.y+a1.y)+(a2.y+a3.y)) + ((a4.y+a5.y)+(a6.y+a7.y))) / (float)kSVIT;
    r.z = (((a0.z+a1.z)+(a2.z+a3.z)) + ((a4.z+a5.z)+(a6.z+a7.z))) / (float)kSVIT;
    r.w = (((a0.w+a1.w)+(a2.w+a3.w)) + ((a4.w+a5.w)+(a6.w+a7.w))) / (float)kSVIT;
    reinterpret_cast<float4*>(g_xv)[b * kIMG4 + c] = r;
}

// ---------------- K3: qformer mean over axis 1, float4 wide --------------
__global__ void __launch_bounds__(128) k_q_mean(const float* __restrict__ qf) {
    int tid = blockIdx.x * 128 + threadIdx.x;         // 0 .. 64*192-1
    int b = tid / kHID4;
    int c = tid % kHID4;
    const float4* p = reinterpret_cast<const float4*>(qf) + (size_t)b * kSQ * kHID4 + c;
    float4 a0 = make_float4(0,0,0,0), a1 = a0, a2 = a0, a3 = a0;
    #pragma unroll
    for (int s = 0; s < kSQ; s += 4) {
        f4add(a0, p[(s+0) * kHID4]);
        f4add(a1, p[(s+1) * kHID4]);
        f4add(a2, p[(s+2) * kHID4]);
        f4add(a3, p[(s+3) * kHID4]);
    }
    float4 r;
    r.x = ((a0.x+a1.x)+(a2.x+a3.x)) / (float)kSQ;
    r.y = ((a0.y+a1.y)+(a2.y+a3.y)) / (float)kSQ;
    r.z = ((a0.z+a1.z)+(a2.z+a3.z)) / (float)kSQ;
    r.w = ((a0.w+a1.w)+(a2.w+a3.w)) / (float)kSQ;
    reinterpret_cast<float4*>(g_xq)[b * kHID4 + c] = r;
}

// ---------------- K4: small MLP heads (exact fp32 FMA) ------------------
__global__ void __launch_bounds__(192) k_heads(
        const float* __restrict__ Wmu1, const float* __restrict__ bmu1,
        const float* __restrict__ Wlv1, const float* __restrict__ blv1,
        const float* __restrict__ Wt1,  const float* __restrict__ bt1,
        const float* __restrict__ Wt2,  const float* __restrict__ bt2,
        const int*   __restrict__ rand_idx) {
    int b = blockIdx.x, t = threadIdx.x;
    __shared__ float s_h0[kHM], s_h1[kHM];

    if (t < 64) {
        int j = t & 31;
        const float* W  = (t < 32) ? Wmu1 : Wlv1;
        const float* bb = (t < 32) ? bmu1 : blv1;
        const float* xq = g_xq + b * kHID;
        float a0 = 0.f, a1 = 0.f, a2 = 0.f, a3 = 0.f;
        #pragma unroll 4
        for (int k = 0; k < kHID; k += 4) {
            a0 = fmaf(xq[k+0], W[(k+0) * kHC + j], a0);
            a1 = fmaf(xq[k+1], W[(k+1) * kHC + j], a1);
            a2 = fmaf(xq[k+2], W[(k+2) * kHC + j], a2);
            a3 = fmaf(xq[k+3], W[(k+3) * kHC + j], a3);
        }
        float h = fmaxf((((a0+a1)+(a2+a3)) + bb[j]), 0.f);
        if (t < 32) g_hmu[b * kHC + j] = h;
        else        g_hlv[b * kHC + j] = h;
    } else {
        int u = (t - 64) & 63;
        int qrow = (t < 128) ? b : rand_idx[b];
        const float* xv = g_xv + (size_t)b    * kIMG;
        const float* xq = g_xq + (size_t)qrow * kHID;
        float a0 = 0.f, a1 = 0.f, a2 = 0.f, a3 = 0.f;
        #pragma unroll 4
        for (int k = 0; k < kIMG; k += 4) {
            a0 = fmaf(xv[k+0], Wt1[(k+0) * kHM + u], a0);
            a1 = fmaf(xv[k+1], Wt1[(k+1) * kHM + u], a1);
            a2 = fmaf(xv[k+2], Wt1[(k+2) * kHM + u], a2);
            a3 = fmaf(xv[k+3], Wt1[(k+3) * kHM + u], a3);
        }
        #pragma unroll 4
        for (int k = 0; k < kHID; k += 4) {
            a0 = fmaf(xq[k+0], Wt1[(kIMG+k+0) * kHM + u], a0);
            a1 = fmaf(xq[k+1], Wt1[(kIMG+k+1) * kHM + u], a1);
            a2 = fmaf(xq[k+2], Wt1[(kIMG+k+2) * kHM + u], a2);
            a3 = fmaf(xq[k+3], Wt1[(kIMG+k+3) * kHM + u], a3);
        }
        float h = fmaxf((((a0+a1)+(a2+a3)) + bt1[u]), 0.f);
        if (t < 128) s_h0[u] = h;
        else         s_h1[u] = h;
    }
    __syncthreads();
    // T0/T1 final dot: sequential fp32 FMA (k-order), bias after — unchanged
    if (t == 0) {
        float a = 0.f, c2 = 0.f;
        for (int u = 0; u < kHM; u++) {
            float w = Wt2[u];
            a  = fmaf(s_h0[u], w, a);
            c2 = fmaf(s_h1[u], w, c2);
        }
        g_T0[b] = a  + bt2[0];
        g_T1[b] = c2 + bt2[0];
    }
}

// ---------------- K5: I_zy — sparse-aware scan over (b,c) ----------------
__global__ void k_izy(const float* __restrict__ Wmu2, const float* __restrict__ bmu2,
                      const float* __restrict__ Wlv2, const float* __restrict__ blv2,
                      const int*   __restrict__ perm_idx) {
    __shared__ float s_hmu[kB * kHC];
    __shared__ float s_hlv[kB * kHC];
    __shared__ int   s_perm[kB];
    int tx = threadIdx.x;
    for (int i = tx; i < kB * kHC; i += blockDim.x) {
        s_hmu[i] = g_hmu[i];
        s_hlv[i] = g_hlv[i];
    }
    if (tx < kB) s_perm[tx] = perm_idx[tx];
    __syncthreads();

    int c = blockIdx.x * blockDim.x + tx;
    double acc = 0.0;
    if (c < kC) {
        float wm[kHC], wl[kHC];
        #pragma unroll
        for (int j = 0; j < kHC; j++) {
            wm[j] = Wmu2[j * kC + c];
            wl[j] = Wlv2[j * kC + c];
        }
        float bm = bmu2[c], bl = blv2[c];
        for (int b = 0; b < kB; b++) {
            float y  = g_hist[b * kC + c];
            float yp = g_hist[s_perm[b] * kC + c];
            if (y != 0.f || yp != 0.f) {
                y  *= (1.f / kL);
                yp *= (1.f / kL);
                float mu = 0.f, lv = 0.f;
                #pragma unroll
                for (int j = 0; j < kHC; j++) {
                    mu = fmaf(s_hmu[b * kHC + j], wm[j], mu);
                    lv = fmaf(s_hlv[b * kHC + j], wl[j], lv);
                }
                mu += bm;
                lv = tanhf(lv + bl);
                float iv = 1.f / (expf(lv) + 1e-6f);
                float dp = mu - y;
                float dn = mu - yp;
                acc += (double)((dn * dn - dp * dp) * iv);
            }
        }
    }

    __shared__ double red[128];
    red[tx] = acc;
    __syncthreads();
    for (int s = 64; s > 0; s >>= 1) {
        if (tx < s) red[tx] += red[tx + s];
        __syncthreads();
    }
    if (tx == 0) atomicAdd(&g_acc, red[0]);
}

// ---------------- K6: finalize — parallel CR exps, strict fp32 tail ------
__global__ void k_final(float* __restrict__ out) {
    int t = threadIdx.x;                 // 64 threads
    __shared__ float s_e[kB];
    __shared__ float s_amax;

    if (t == 0) {                        // amax exact (max is order-free)
        float m = g_T1[0];
        for (int b = 1; b < kB; b++) m = fmaxf(m, g_T1[b]);
        s_amax = m;
    }
    __syncthreads();
    // parallel correctly-rounded fp32 exp via double (identical values)
    {
        float x = g_T1[t] - s_amax;
        s_e[t] = (float)exp((double)x);
    }
    __syncthreads();
    if (t == 0) {
        // strict sequential fp32 sums — same order as before
        float esum = 0.f, t0sum = 0.f;
        for (int b = 0; b < kB; b++) {
            esum  = esum + s_e[b];
            t0sum = t0sum + g_T0[b];
        }
        float t0m  = t0sum / 64.0f;
        float lgs  = (float)log((double)esum);
        float lse  = lgs + s_amax;
        float logB = (float)log(64.0);
        float d    = lse - logB;
        float ixz  = t0m - d;
        float izy  = (float)g_acc / 128.0f;
        out[0] = izy - 0.1f * ixz;
    }
}

// ---------------- launch ----------------
extern "C" void kernel_launch(void* const* d_in, const int* in_sizes, int n_in,
                              void* d_out, int out_size) {
    const float* vit   = (const float*)d_in[0];
    const float* qf    = (const float*)d_in[1];
    const int*   label = (const int*)  d_in[2];
    const int*   perm  = (const int*)  d_in[3];
    const int*   rnd   = (const int*)  d_in[4];
    const float* Wmu1  = (const float*)d_in[5];
    const float* bmu1  = (const float*)d_in[6];
    const float* Wmu2  = (const float*)d_in[7];
    const float* bmu2  = (const float*)d_in[8];
    const float* Wlv1  = (const float*)d_in[9];
    const float* blv1  = (const float*)d_in[10];
    const float* Wlv2  = (const float*)d_in[11];
    const float* blv2  = (const float*)d_in[12];
    const float* Wt1   = (const float*)d_in[13];
    const float* bt1   = (const float*)d_in[14];
    const float* Wt2   = (const float*)d_in[15];
    const float* bt2   = (const float*)d_in[16];
    float* out = (float*)d_out;

    k_zero<<<(kB * kC / 4 + 255) / 256, 256>>>();
    k_scatter<<<(kB * kL + 255) / 256, 256>>>(label);
    k_vit_mean<<<(kB * kIMG4) / 64, 64>>>(vit);
    k_q_mean<<<(kB * kHID4) / 128, 128>>>(qf);
    k_heads<<<kB, 192>>>(Wmu1, bmu1, Wlv1, blv1, Wt1, bt1, Wt2, bt2, rnd);
    k_izy<<<(kC + 127) / 128, 128>>>(Wmu2, bmu2, Wlv2, blv2, perm);
    k_final<<<1, 64>>>(out);
}

// round 7
// speedup vs baseline: 3.0419x; 2.9040x over previous
#include <cuda_runtime.h>
#include <math.h>

// ---------------- problem constants ----------------
constexpr int kB    = 64;
constexpr int kSVIT = 257;
constexpr int kSQ   = 32;
constexpr int kL    = 512;
constexpr int kIMG  = 1408;
constexpr int kHID  = 768;
constexpr int kC    = 30000;
constexpr int kHC   = 32;   // H_CLUB
constexpr int kHM   = 64;   // H_MINE

constexpr int kIMG4 = kIMG / 4;   // 352 float4 columns
constexpr int kHID4 = kHID / 4;   // 192 float4 columns

// ---------------- scratch (device globals; no allocation) ----------------
__device__ __align__(16) float  g_hist[kB * kC];
__device__ __align__(16) float  g_xv[kB * kIMG];
__device__ __align__(16) float  g_xq[kB * kHID];
__device__ __align__(16) float  g_hmu[kB * kHC];
__device__ __align__(16) float  g_hlv[kB * kHC];
__device__ float  g_T0[kB];
__device__ float  g_T1[kB];
__device__ double g_acc;

__device__ __forceinline__ void f4add(float4& a, const float4 v) {
    a.x += v.x; a.y += v.y; a.z += v.z; a.w += v.w;
}

// ---------------- K0: zero hist + accumulator ----------------
__global__ void k_zero() {
    int idx = blockIdx.x * blockDim.x + threadIdx.x;
    float4* p = reinterpret_cast<float4*>(g_hist);
    if (idx < (kB * kC) / 4) p[idx] = make_float4(0.f, 0.f, 0.f, 0.f);
    if (idx == 0) g_acc = 0.0;
}

// ---------------- K1: scatter labels into histogram ----------------
__global__ void k_scatter(const int* __restrict__ label) {
    int i = blockIdx.x * blockDim.x + threadIdx.x;
    if (i < kB * kL) {
        int l = label[i];
        if (l == -100) l = 0;
        int b = i / kL;
        atomicAdd(&g_hist[b * kC + l], 1.0f);
    }
}

// ---------------- K2: vit mean — 8 s-lanes per column, 180K threads ------
// Lane i sums s = i, i+8, ... ascending. For i=0 that sequence is
// 0,8,...,248,256 — identical to the old a0 (main loop + tail fold).
// Combine tree identical: ((A0+A1)+(A2+A3)) + ((A4+A5)+(A6+A7)).
__global__ void __launch_bounds__(256) k_vit_mean(const float* __restrict__ vit) {
    int tx = threadIdx.x & 31;    // column within group
    int ty = threadIdx.x >> 5;    // s-lane 0..7
    int b  = blockIdx.y;
    int c  = blockIdx.x * 32 + tx;
    const float4* p = reinterpret_cast<const float4*>(vit) + (size_t)b * kSVIT * kIMG4 + c;
    float4 a = make_float4(0.f, 0.f, 0.f, 0.f);
    for (int s = ty; s < kSVIT; s += 8)
        f4add(a, p[(size_t)s * kIMG4]);
    __shared__ float4 sm[8][32];
    sm[ty][tx] = a;
    __syncthreads();
    if (ty == 0) {
        float4 A0 = sm[0][tx], A1 = sm[1][tx], A2 = sm[2][tx], A3 = sm[3][tx];
        float4 A4 = sm[4][tx], A5 = sm[5][tx], A6 = sm[6][tx], A7 = sm[7][tx];
        float4 r;
        r.x = (((A0.x+A1.x)+(A2.x+A3.x)) + ((A4.x+A5.x)+(A6.x+A7.x))) / (float)kSVIT;
        r.y = (((A0.y+A1.y)+(A2.y+A3.y)) + ((A4.y+A5.y)+(A6.y+A7.y))) / (float)kSVIT;
        r.z = (((A0.z+A1.z)+(A2.z+A3.z)) + ((A4.z+A5.z)+(A6.z+A7.z))) / (float)kSVIT;
        r.w = (((A0.w+A1.w)+(A2.w+A3.w)) + ((A4.w+A5.w)+(A6.w+A7.w))) / (float)kSVIT;
        reinterpret_cast<float4*>(g_xv)[b * kIMG4 + c] = r;
    }
}

// ---------------- K3: qformer mean — 4 s-lanes per column ----------------
__global__ void __launch_bounds__(128) k_q_mean(const float* __restrict__ qf) {
    int tx = threadIdx.x & 31;    // column within group
    int ty = threadIdx.x >> 5;    // s-lane 0..3
    int b  = blockIdx.y;
    int c  = blockIdx.x * 32 + tx;
    const float4* p = reinterpret_cast<const float4*>(qf) + (size_t)b * kSQ * kHID4 + c;
    float4 a = make_float4(0.f, 0.f, 0.f, 0.f);
    #pragma unroll
    for (int s = 0; s < kSQ; s += 4)
        f4add(a, p[(size_t)(s + ty) * kHID4]);
    __shared__ float4 sm[4][32];
    sm[ty][tx] = a;
    __syncthreads();
    if (ty == 0) {
        float4 A0 = sm[0][tx], A1 = sm[1][tx], A2 = sm[2][tx], A3 = sm[3][tx];
        float4 r;
        r.x = ((A0.x+A1.x)+(A2.x+A3.x)) / (float)kSQ;
        r.y = ((A0.y+A1.y)+(A2.y+A3.y)) / (float)kSQ;
        r.z = ((A0.z+A1.z)+(A2.z+A3.z)) / (float)kSQ;
        r.w = ((A0.w+A1.w)+(A2.w+A3.w)) / (float)kSQ;
        reinterpret_cast<float4*>(g_xq)[b * kHID4 + c] = r;
    }
}

// ---------------- K4: small MLP heads — 4 k-lanes per output unit --------
// Each accumulator a_i (k ≡ i mod 4, ascending) is its own thread; the
// combine tree ((a0+a1)+(a2+a3)) + bias, relu, and the final sequential
// T dot are unchanged from the passing kernel.
__global__ void __launch_bounds__(768) k_heads(
        const float* __restrict__ Wmu1, const float* __restrict__ bmu1,
        const float* __restrict__ Wlv1, const float* __restrict__ blv1,
        const float* __restrict__ Wt1,  const float* __restrict__ bt1,
        const float* __restrict__ Wt2,  const float* __restrict__ bt2,
        const int*   __restrict__ rand_idx) {
    int b = blockIdx.x, t = threadIdx.x;
    __shared__ float s_club[4][64];   // [lane][head*32+j]
    __shared__ float s_mine[4][128];  // [lane][which*64+u]
    __shared__ float s_h0[kHM], s_h1[kHM];

    if (t < 256) {
        // CLUB layer 1: lane-major so consecutive threads share a warp over j
        int lane = t >> 6;            // k-lane 0..3
        int idx  = t & 63;            // head*32 + j
        int j    = idx & 31;
        const float* W  = (idx < 32) ? Wmu1 : Wlv1;
        const float* xq = g_xq + b * kHID;
        float a = 0.f;
        for (int k = lane; k < kHID; k += 4)
            a = fmaf(xq[k], W[k * kHC + j], a);
        s_club[lane][idx] = a;
    } else {
        // MINE layer 1
        int m    = t - 256;
        int lane = m >> 7;            // k-lane 0..3
        int idx  = m & 127;           // which*64 + u
        int u    = idx & 63;
        int qrow = (idx < 64) ? b : rand_idx[b];
        const float* xv = g_xv + (size_t)b    * kIMG;
        const float* xq = g_xq + (size_t)qrow * kHID;
        float a = 0.f;
        for (int k = lane; k < kIMG; k += 4)
            a = fmaf(xv[k], Wt1[k * kHM + u], a);
        for (int k = lane; k < kHID; k += 4)
            a = fmaf(xq[k], Wt1[(kIMG + k) * kHM + u], a);
        s_mine[lane][idx] = a;
    }
    __syncthreads();

    if (t < 64) {
        // combine CLUB: tree + bias + relu (identical association)
        int j = t & 31;
        const float* bb = (t < 32) ? bmu1 : blv1;
        float h = fmaxf(((s_club[0][t] + s_club[1][t]) +
                         (s_club[2][t] + s_club[3][t])) + bb[j], 0.f);
        if (t < 32) g_hmu[b * kHC + j] = h;
        else        g_hlv[b * kHC + j] = h;
    } else if (t < 192) {
        int idx = t - 64;             // which*64 + u
        int u = idx & 63;
        float h = fmaxf(((s_mine[0][idx] + s_mine[1][idx]) +
                         (s_mine[2][idx] + s_mine[3][idx])) + bt1[u], 0.f);
        if (idx < 64) s_h0[u] = h;
        else          s_h1[u] = h;
    }
    __syncthreads();
    // T0/T1 final dot: sequential fp32 FMA (k-order), bias after — unchanged
    if (t == 0) {
        float a = 0.f, c2 = 0.f;
        for (int u = 0; u < kHM; u++) {
            float w = Wt2[u];
            a  = fmaf(s_h0[u], w, a);
            c2 = fmaf(s_h1[u], w, c2);
        }
        g_T0[b] = a  + bt2[0];
        g_T1[b] = c2 + bt2[0];
    }
}

// ---------------- K5: I_zy — sparse-aware scan, batched hist loads -------
__global__ void k_izy(const float* __restrict__ Wmu2, const float* __restrict__ bmu2,
                      const float* __restrict__ Wlv2, const float* __restrict__ blv2,
                      const int*   __restrict__ perm_idx) {
    __shared__ float s_hmu[kB * kHC];
    __shared__ float s_hlv[kB * kHC];
    __shared__ int   s_perm[kB];
    int tx = threadIdx.x;
    for (int i = tx; i < kB * kHC; i += blockDim.x) {
        s_hmu[i] = g_hmu[i];
        s_hlv[i] = g_hlv[i];
    }
    if (tx < kB) s_perm[tx] = perm_idx[tx];
    __syncthreads();

    int c = blockIdx.x * blockDim.x + tx;
    double acc = 0.0;
    if (c < kC) {
        float wm[kHC], wl[kHC];
        #pragma unroll
        for (int j = 0; j < kHC; j++) {
            wm[j] = Wmu2[j * kC + c];
            wl[j] = Wlv2[j * kC + c];
        }
        float bm = bmu2[c], bl = blv2[c];
        for (int b0 = 0; b0 < kB; b0 += 8) {
            float ys[8], yps[8];
            #pragma unroll
            for (int j = 0; j < 8; j++) {
                ys[j]  = g_hist[(b0 + j) * kC + c];
                yps[j] = g_hist[s_perm[b0 + j] * kC + c];
            }
            #pragma unroll
            for (int q = 0; q < 8; q++) {
                int b = b0 + q;
                float y = ys[q], yp = yps[q];
                if (y != 0.f || yp != 0.f) {
                    y  *= (1.f / kL);
                    yp *= (1.f / kL);
                    float mu = 0.f, lv = 0.f;
                    #pragma unroll
                    for (int j = 0; j < kHC; j++) {
                        mu = fmaf(s_hmu[b * kHC + j], wm[j], mu);
                        lv = fmaf(s_hlv[b * kHC + j], wl[j], lv);
                    }
                    mu += bm;
                    lv = tanhf(lv + bl);
                    float iv = 1.f / (expf(lv) + 1e-6f);
                    float dp = mu - y;
                    float dn = mu - yp;
                    acc += (double)((dn * dn - dp * dp) * iv);
                }
            }
        }
    }

    __shared__ double red[128];
    red[tx] = acc;
    __syncthreads();
    for (int s = 64; s > 0; s >>= 1) {
        if (tx < s) red[tx] += red[tx + s];
        __syncthreads();
    }
    if (tx == 0) atomicAdd(&g_acc, red[0]);
}

// ---------------- K6: finalize — parallel CR exps, strict fp32 tail ------
__global__ void k_final(float* __restrict__ out) {
    int t = threadIdx.x;                 // 64 threads
    __shared__ float s_e[kB];
    __shared__ float s_amax;

    if (t == 0) {                        // amax exact (max is order-free)
        float m = g_T1[0];
        for (int b = 1; b < kB; b++) m = fmaxf(m, g_T1[b]);
        s_amax = m;
    }
    __syncthreads();
    {
        float x = g_T1[t] - s_amax;
        s_e[t] = (float)exp((double)x);  // CR fp32 exp via double
    }
    __syncthreads();
    if (t == 0) {
        float esum = 0.f, t0sum = 0.f;
        for (int b = 0; b < kB; b++) {   // strict sequential fp32 sums
            esum  = esum + s_e[b];
            t0sum = t0sum + g_T0[b];
        }
        float t0m  = t0sum / 64.0f;
        float lgs  = (float)log((double)esum);
        float lse  = lgs + s_amax;
        float logB = (float)log(64.0);
        float d    = lse - logB;
        float ixz  = t0m - d;
        float izy  = (float)g_acc / 128.0f;
        out[0] = izy - 0.1f * ixz;
    }
}

// ---------------- launch ----------------
extern "C" void kernel_launch(void* const* d_in, const int* in_sizes, int n_in,
                              void* d_out, int out_size) {
    const float* vit   = (const float*)d_in[0];
    const float* qf    = (const float*)d_in[1];
    const int*   label = (const int*)  d_in[2];
    const int*   perm  = (const int*)  d_in[3];
    const int*   rnd   = (const int*)  d_in[4];
    const float* Wmu1  = (const float*)d_in[5];
    const float* bmu1  = (const float*)d_in[6];
    const float* Wmu2  = (const float*)d_in[7];
    const float* bmu2  = (const float*)d_in[8];
    const float* Wlv1  = (const float*)d_in[9];
    const float* blv1  = (const float*)d_in[10];
    const float* Wlv2  = (const float*)d_in[11];
    const float* blv2  = (const float*)d_in[12];
    const float* Wt1   = (const float*)d_in[13];
    const float* bt1   = (const float*)d_in[14];
    const float* Wt2   = (const float*)d_in[15];
    const float* bt2   = (const float*)d_in[16];
    float* out = (float*)d_out;

    k_zero<<<(kB * kC / 4 + 255) / 256, 256>>>();
    k_scatter<<<(kB * kL + 255) / 256, 256>>>(label);
    k_vit_mean<<<dim3(kIMG4 / 32, kB), 256>>>(vit);
    k_q_mean<<<dim3(kHID4 / 32, kB), 128>>>(qf);
    k_heads<<<kB, 768>>>(Wmu1, bmu1, Wlv1, blv1, Wt1, bt1, Wt2, bt2, rnd);
    k_izy<<<(kC + 127) / 128, 128>>>(Wmu2, bmu2, Wlv2, blv2, perm);
    k_final<<<1, 64>>>(out);
}